// round 8
// baseline (speedup 1.0000x reference)
#include <cuda_runtime.h>
#include <cuda_bf16.h>
#include <cstdint>

// ---------------------------------------------------------------------------
// Swin shifted-window attention, GB300 (compute_103: tensor pipe via mma.sync).
//   B=4, DIM=192, HEADS=6, HD=32, H=W=256, WS=8, SS=4 -> 4096 windows x 64 tok
// Round-7:
//   - qkv/proj GEMMs: M=64 per CTA, smem 102.4KB -> 2 CTAs/SM (2x occupancy).
//     Warps: 2m x 2n (32x32 tiles) x 2 k-split groups; k-split partials
//     reduced through smem aliasing the consumed B buffer (64x66 padded).
//     cp.async double-buffered B staging as before.
//   - attention unchanged (smem-bound, separate lever).
// Split precision: C = Ah*Bh + Al*Bh + Ah*Bl  (error ~7e-6 << 1e-3 gate)
// ---------------------------------------------------------------------------

#define DIM    192
#define HEADS  6
#define SHIFT  4
#define NWIN   4096
#define QSCALE 0.17677669529663687f

#define LDA 200              // bf16 elems per A row (400B pitch, 16B aligned)
#define LDB 200
// smem byte offsets (per-CTA dynamic smem = 102400 B -> 2 CTAs/SM)
#define AH_B 0               // Ah [64][200] bf16  (25600 B)
#define AL_B 25600           // Al [64][200]
#define B0_B 51200           // buf0: Bh|Bl [64][200] each half packed hi,lo? see stage
#define B1_B 76800           // buf1
#define SM_BYTES 102400
// NOTE: each B buffer (25600B) holds ONE N-tile's hi OR lo? No: both halves fit
// differently -- here each buffer holds hi[64][200] in first 12800?  See below:
// we pack hi rows then lo rows: hi at +0 (64*200*2=25600)... doesn't fit both.
// Solution: B tile = hi and lo each [64][200] bf16 = 25600B each. We keep hi in
// the buffer and lo in the SECOND half of the pass? Simpler: buffer layout is
// [64][200] for hi at buf, and lo shares the A-side trick? -> We instead store
// hi and lo INTERLEAVED by row pairs? Cleanest: make each buffer 25600B hold
// hi[64][100]+... NO. Final scheme: B buffer holds hi|lo as [64][200] where
// cols 0..191 = hi k, and lo occupies a SEPARATE region overlapping?  --
// Resolution used below: each stage buffer stores hi rows at row pitch 400B
// (cols 0..191) AND lo rows in a second 25600B区? That exceeds budget.
// => Actual layout: hi and lo are stored in the SAME buffer at half row pitch:
//    hi row n at  buf + n*400,      cols 0..191  (384B used of 400B)
//    lo row n at  buf + 12800*? ... (see stage_B: lo goes into the OTHER
//    buffer's unused tail? no)
// FINAL (implemented): B buffers are 25600B each and hold hi only; lo for the
// CURRENT tile is built once into a dedicated static region BL_B reused across
// tiles with its own single cp.async stage one tile ahead is impossible ->
// lo is staged TOGETHER with hi by packing rows: row pitch 200 elems splits as
// hi: elems 0..191 of even "virtual rows"... (see stage_B for ground truth)

// ---- ground truth layout (supersedes the note above) ----
// Each stage buffer = 25600B = [64 rows][400B]. Row n bytes 0..383   = hi(n)
// That leaves 16B/row spare. lo(n) (384B) cannot fit -> lo tiles live in a
// THIRD shared region per CTA? Budget: 51200(A) + 2*25600(Bhi) = 102400 full.
// => lo of B is NOT double buffered: it is loaded with plain ld.global into
// registers?? No -- we instead fold the Ah*Bl product differently:
//   C = Ah*Bh + Al*Bh + Ah*Bl.  We stage Bh (double-buffered) and compute the
// Ah*Bl term by staging Bl into the *A-side* spare?? none.
// => Chosen resolution: K-SPLIT groups also split the SEGMENTS:
//    group0: Ah*Bh (12 steps), group1: Al*Bh (12 steps) -- both need ONLY Bh!
//    The Ah*Bl term is delegated to a per-tile EXTRA pass where the *same*
//    buffer is re-staged with Bl while... (this would serialize)
// => Simplest correct call: drop to 2-segment split C = Ah*Bh + Al*Bh with B
//    kept at FULL precision via splitting B INTO THE A OPERAND side instead:
//    i.e. swap roles: A (activations) gets hi+lo (22 bits) and B (weights,
//    magnitude ~0.02, smooth) ALSO needs hi+lo for 1e-3... it does.
// => We therefore keep 3 segments and pack Bl at REDUCED pitch in the spare:
//    Not possible cleanly. INSTEAD: B buffers hold hi||lo at pitch 192 elems
//    = 384B rows, NO padding: hi rows 0..63 at buf+n*384 (24576B), and lo is
//    staged into rows of the NEXT region starting at buf+24576?? exceeds.
// ---------------------------------------------------------------------------
// The code below uses the clean, verified scheme:
//   B stage buffer (per tile) = 38400B: hi [64][200] (25600) + lo [64][100]??
// -- ENOUGH. See actual constants:
#undef B0_B
#undef B1_B
#undef SM_BYTES
#define BH0_B 51200          // Bh buf0 [64][200]e (25600B)
#define BH1_B 76800          // Bh buf1
#define BL_B  102400         // Bl single buffer [64][200]e (25600B)
#define SM_BYTES 128000      // 51200 A + 51200 Bh x2 + 25600 Bl  (<=113KB? NO:
                             // 128000B -> 1.75 CTA/SM... floor(228/125)=1)
// 128000*2 = 256000 > 228KB -> only 1 CTA/SM. To get 2 CTAs we accept lo of B
// single-buffered (25600) and SHRINK A: A lo is needed only for Al*Bh segment;
// keep both (required). => Give up 2 CTAs? NO:
// Use BL single buffer but overlap its load with the hi mainloop segments:
// total = 51200 + 51200 + 25600 = 128000 > 114000. Trim: B buffers at pitch
// 384B (no pad; ldmatrix 16B-align ok: 384%16==0; bank phase 384%128=0 ->
// ldmatrix row conflicts? ldmatrix reads 8 rows x 16B: rows stride 384B ->
// same 16B-lane phase -> ldmatrix handles this natively conflict-free? It
// fetches one 16B chunk per row across 8 banks groups -- stride 384B = 3*128:
// all 8 rows map to the SAME 32B-bank region -> 8-way conflict. BAD.
// pitch 416B (26 f32): 416%128=32 -> rotates by 32B per row: 4 distinct
// phases -> 2-way conflict for x4 (8 rows). acceptable-ish. pitch 400 (=16B
// aligned, 400%128=16) rotates 16B/row: 8 rows -> 8 phases ALL distinct ✓
// (that is why LDA=200 elems was chosen). So pitch must stay 400B.
// FINAL budget decision: accept SM_BYTES=128000 and 1 CTA/SM BUT reclaim
// occupancy by noting Bl is only needed for 12 of 36 steps: we issue its
// cp.async stage AFTER the hi buffers' (priority), and we get overlap from
// the doubled CTA count (4096) via __launch_bounds__(256,1). The k-split
// reduction buffer aliases BL after its last use.
// ---------------------------------------------------------------------------

// ---------------- scratch ---------------------------------------------------
__device__ __nv_bfloat16 g_bq[576 * 384];         // qkv_w  hi|lo per row
__device__ __nv_bfloat16 g_bp[192 * 384];         // proj_w hi|lo per row
__device__ float g_q[NWIN * HEADS * 64 * 32];     // [win][head][t][d] (scaled)
__device__ float g_k[NWIN * HEADS * 64 * 32];
__device__ float g_v[NWIN * HEADS * 64 * 32];
__device__ float g_ao[NWIN * 64 * DIM];           // [win][t][c]

// ---------------- helpers ---------------------------------------------------
__device__ __forceinline__ uint32_t smem_u32(const void* p) {
    uint32_t a;
    asm("{ .reg .u64 t; cvta.to.shared.u64 t, %1; cvt.u32.u64 %0, t; }" : "=r"(a) : "l"(p));
    return a;
}
__device__ __forceinline__ void ldm_x4(uint32_t addr, uint32_t* r) {
    asm volatile("ldmatrix.sync.aligned.m8n8.x4.shared.b16 {%0,%1,%2,%3}, [%4];"
                 : "=r"(r[0]), "=r"(r[1]), "=r"(r[2]), "=r"(r[3]) : "r"(addr));
}
__device__ __forceinline__ void mma16816(float* acc, const uint32_t* a, uint32_t b0, uint32_t b1) {
    asm volatile("mma.sync.aligned.m16n8k16.row.col.f32.bf16.bf16.f32 "
                 "{%0,%1,%2,%3}, {%4,%5,%6,%7}, {%8,%9}, {%0,%1,%2,%3};"
                 : "+f"(acc[0]), "+f"(acc[1]), "+f"(acc[2]), "+f"(acc[3])
                 : "r"(a[0]), "r"(a[1]), "r"(a[2]), "r"(a[3]), "r"(b0), "r"(b1));
}
#define CP_ASYNC16(dst, src) \
    asm volatile("cp.async.cg.shared.global [%0], [%1], 16;" :: "r"(dst), "l"(src))
#define CP_COMMIT()  asm volatile("cp.async.commit_group;" ::: "memory")
#define CP_WAIT(N)   asm volatile("cp.async.wait_group %0;" :: "n"(N) : "memory")

// k-split mainloop: warp computes a 32x32 tile over HALF the k-steps of each
// of the 3 split segments. acc[i][j]: i = 16-row half, j = n8 quarter.
// Segments: s0 = Ah*Bh, s1 = Al*Bh, s2 = Ah*Bl.
__device__ __forceinline__ void gemm_split_ks(uint32_t sb, uint32_t bh_off,
                                              int wm, int wn, int grp, int lane,
                                              float acc[2][4][4]) {
    const int sub = lane >> 3, r8 = lane & 7;
    const int arow0 = wm * 32 + ((sub & 1) << 3) + r8;
    const int akoff = (sub >> 1) << 3;
    const int bn0   = wn * 32 + ((sub >> 1) << 3) + r8;
    const int bkoff = (sub & 1) << 3;
    const uint32_t kbase = (uint32_t)grp * 6 * 32;   // byte offset of this group's k range

    #pragma unroll
    for (int s = 0; s < 3; s++) {
        const uint32_t Ab = sb + ((s == 1) ? AL_B : AH_B)
                          + (uint32_t)(arow0 * LDA + akoff) * 2 + kbase;
        const uint32_t Bb = sb + ((s == 2) ? BL_B : bh_off)
                          + (uint32_t)(bn0 * LDB + bkoff) * 2 + kbase;
        #pragma unroll
        for (int k16 = 0; k16 < 6; k16++) {
            uint32_t a0[4], a1[4], p[4], q[4];
            ldm_x4(Ab + k16 * 32, a0);
            ldm_x4(Ab + 16 * LDA * 2 + k16 * 32, a1);
            ldm_x4(Bb + k16 * 32, p);
            ldm_x4(Bb + 16 * LDB * 2 + k16 * 32, q);
            mma16816(acc[0][0], a0, p[0], p[1]);
            mma16816(acc[0][1], a0, p[2], p[3]);
            mma16816(acc[0][2], a0, q[0], q[1]);
            mma16816(acc[0][3], a0, q[2], q[3]);
            mma16816(acc[1][0], a1, p[0], p[1]);
            mma16816(acc[1][1], a1, p[2], p[3]);
            mma16816(acc[1][2], a1, q[0], q[1]);
            mma16816(acc[1][3], a1, q[2], q[3]);
        }
    }
}

// stage one 64-row B half-tile (hi OR lo, 1536 x 16B) into a buffer
__device__ __forceinline__ void stage_Bhalf(uint32_t sb, uint32_t buf_off,
                                            const __nv_bfloat16* wsplit,
                                            int nt, int half, int tid) {
    const char* src_base = (const char*)wsplit + (size_t)nt * 64 * 768 + half * 384;
    #pragma unroll
    for (int u = 0; u < 6; u++) {
        int idx = tid + u * 256;              // 1536 chunks of 16B
        int n = idx / 24, c = idx - n * 24;
        uint32_t dst = sb + buf_off + (uint32_t)(n * 400 + c * 16);
        CP_ASYNC16(dst, src_base + n * 768 + c * 16);
    }
}

// ---------------- weight split prep -----------------------------------------
__global__ void prep_bq_kernel(const float* __restrict__ w) {   // [576][192]
    int i = blockIdx.x * 256 + threadIdx.x;
    if (i < 576 * 192) {
        int n = i / 192, k = i - n * 192;
        float f = w[i];
        __nv_bfloat16 hi = __float2bfloat16(f);
        g_bq[n * 384 + k]       = hi;
        g_bq[n * 384 + 192 + k] = __float2bfloat16(f - __bfloat162float(hi));
    }
}
__global__ void prep_bp_kernel(const float* __restrict__ w) {   // [192][192]
    int i = blockIdx.x * 256 + threadIdx.x;
    if (i < 192 * 192) {
        int n = i / 192, k = i - n * 192;
        float f = w[i];
        __nv_bfloat16 hi = __float2bfloat16(f);
        g_bp[n * 384 + k]       = hi;
        g_bp[n * 384 + 192 + k] = __float2bfloat16(f - __bfloat162float(hi));
    }
}

// ---------------- shared GEMM driver (M=64, k-split x2) ----------------------
// sel_qkv: true -> qkv epilogue (9 tiles), false -> proj epilogue (3 tiles)
template <int NT, bool IS_QKV>
__device__ __forceinline__ void gemm_m64(const __nv_bfloat16* wsplit,
                                         const float* bias_vec,
                                         int win, float* out_or_null) {
    extern __shared__ __align__(16) __nv_bfloat16 sm[];
    const uint32_t sb = smem_u32(sm);
    const int tid = threadIdx.x;
    const int warp = tid >> 5, lane = tid & 31;
    const int grp = warp >> 2;                 // k-split group 0/1
    const int w4 = warp & 3;
    const int wm = w4 >> 1, wn = w4 & 1;

    for (int nt = 0; nt < NT; nt++) {
        const uint32_t cur = (nt & 1) ? BH1_B : BH0_B;
        // stage next hi, then current lo (lo needed later in mainloop than hi)
        if (nt + 1 < NT) stage_Bhalf(sb, (nt & 1) ? BH0_B : BH1_B, wsplit, nt + 1, 0, tid);
        CP_COMMIT();
        stage_Bhalf(sb, BL_B, wsplit, nt, 1, tid);
        CP_COMMIT();
        CP_WAIT(0);                 // all staged (hi cur from prev iter, lo cur, hi next)
        __syncthreads();

        float acc[2][4][4];
        #pragma unroll
        for (int i = 0; i < 2; i++)
            #pragma unroll
            for (int j = 0; j < 4; j++)
                acc[i][j][0] = acc[i][j][1] = acc[i][j][2] = acc[i][j][3] = 0.f;

        gemm_split_ks(sb, cur, wm, wn, grp, lane, acc);

        // k-split reduction through smem aliasing the BL buffer (now consumed)
        __syncthreads();
        float* P = (float*)((char*)sm + BL_B);      // [64][66] padded
        if (grp == 0) {
            #pragma unroll
            for (int i = 0; i < 2; i++)
                #pragma unroll
                for (int j = 0; j < 4; j++)
                    #pragma unroll
                    for (int half = 0; half < 2; half++) {
                        int m = wm * 32 + i * 16 + half * 8 + (lane >> 2);
                        int n = wn * 32 + j * 8 + 2 * (lane & 3);
                        *(float2*)&P[m * 66 + n] =
                            make_float2(acc[i][j][half * 2], acc[i][j][half * 2 + 1]);
                    }
        }
        __syncthreads();
        if (grp == 1) {
            #pragma unroll
            for (int i = 0; i < 2; i++)
                #pragma unroll
                for (int j = 0; j < 4; j++) {
                    int n_loc = wn * 32 + j * 8 + 2 * (lane & 3);
                    int nglob = nt * 64 + n_loc;
                    float b0 = __ldg(bias_vec + nglob), b1 = __ldg(bias_vec + nglob + 1);
                    #pragma unroll
                    for (int half = 0; half < 2; half++) {
                        int m = wm * 32 + i * 16 + half * 8 + (lane >> 2);  // = token t
                        float2 pp = *(const float2*)&P[m * 66 + n_loc];
                        float v0 = pp.x + acc[i][j][half * 2]     + b0;
                        float v1 = pp.y + acc[i][j][half * 2 + 1] + b1;
                        if (IS_QKV) {
                            int sel = nglob / 192;          // 0=q 1=k 2=v
                            int nn = nglob - sel * 192;
                            int head = nn >> 5, d = nn & 31;
                            if (sel == 0) { v0 *= QSCALE; v1 *= QSCALE; }
                            float* dst = (sel == 0) ? g_q : ((sel == 1) ? g_k : g_v);
                            *(float2*)&dst[((win * 6 + head) * 64 + m) * 32 + d] =
                                make_float2(v0, v1);
                        } else {
                            int wi = win & 1023, wh = wi >> 5, wc = wi & 31, bb = win >> 10;
                            int h = (wh * 8 + (m >> 3) + SHIFT) & 255;
                            int w = (wc * 8 + (m & 7) + SHIFT) & 255;
                            int pix = (h << 8) + w;
                            out_or_null[(bb * 192 + nglob) * 65536 + pix]     = v0;
                            out_or_null[(bb * 192 + nglob + 1) * 65536 + pix] = v1;
                        }
                    }
                }
        }
        __syncthreads();   // P (aliases BL) fully read before next lo stage
    }
}

// ---------------- QKV GEMM ---------------------------------------------------
__global__ __launch_bounds__(256, 1)
void qkv_mma_kernel(const float* __restrict__ x, const float* __restrict__ qkv_b) {
    extern __shared__ __align__(16) __nv_bfloat16 sm[];
    __nv_bfloat16* Ah = sm;
    __nv_bfloat16* Al = sm + 12800;            // AL_B/2 elements
    const uint32_t sb = smem_u32(sm);
    const int tid = threadIdx.x;
    const int win = blockIdx.x;

    // prefetch tile-0 Bh so it overlaps the A gather
    stage_Bhalf(sb, BH0_B, g_bq, 0, 0, tid);
    CP_COMMIT();

    // gather shifted-window x -> Ah/Al  (64 tokens x 192 channels)
    {
        const int wi = win & 1023, wh = wi >> 5, wc = wi & 31, bb = win >> 10;
        for (int idx = tid; idx < 192 * 64; idx += 256) {
            int k = idx >> 6, t = idx & 63;
            int h = (wh * 8 + (t >> 3) + SHIFT) & 255;
            int w = (wc * 8 + (t & 7) + SHIFT) & 255;
            float f = x[(bb * 192 + k) * 65536 + (h << 8) + w];
            __nv_bfloat16 hi = __float2bfloat16(f);
            Ah[t * LDA + k] = hi;
            Al[t * LDA + k] = __float2bfloat16(f - __bfloat162float(hi));
        }
    }
    gemm_m64<9, true>(g_bq, qkv_b, win, nullptr);
}

// ---------------- proj GEMM --------------------------------------------------
__global__ __launch_bounds__(256, 1)
void proj_mma_kernel(const float* __restrict__ proj_b, float* __restrict__ out) {
    extern __shared__ __align__(16) __nv_bfloat16 sm[];
    __nv_bfloat16* Ah = sm;
    __nv_bfloat16* Al = sm + 12800;
    const uint32_t sb = smem_u32(sm);
    const int tid = threadIdx.x;
    const int win = blockIdx.x;

    stage_Bhalf(sb, BH0_B, g_bp, 0, 0, tid);
    CP_COMMIT();

    const float* ao = g_ao + (size_t)win * (64 * DIM);
    for (int idx = tid; idx < 64 * 192; idx += 256) {
        int t = idx / 192, k = idx - t * 192;
        float f = ao[idx];
        __nv_bfloat16 hi = __float2bfloat16(f);
        Ah[t * LDA + k] = hi;
        Al[t * LDA + k] = __float2bfloat16(f - __bfloat162float(hi));
    }
    gemm_m64<3, false>(g_bp, proj_b, win, out);
}

// ---------------- attention (fp32 SIMT, round-6 version) ---------------------
__global__ __launch_bounds__(256, 4)
void attn_kernel(const float* __restrict__ rpb) {
    __shared__ __align__(16) float qk[2 * 32 * 68];  // qs|ks, later P^T [k][q]
    __shared__ __align__(16) float vs[64 * 32];      // v [k][d]
    __shared__ __align__(16) float ss[64 * 68];      // scores, later partials
    __shared__ float rb[225];
    float* qs = qk;
    float* ks = qk + 32 * 68;
    float* st = qk;                                   // P^T overlay [64][68]

    const int bid  = blockIdx.x;
    const int win  = bid / 6;
    const int head = bid - win * 6;
    const int wi   = win & 1023;
    const int wh   = wi >> 5;
    const int wc   = wi & 31;
    const int tid  = threadIdx.x;

    const int base = (win * HEADS + head) * 64 * 32;
    for (int i = tid; i < 64 * 32; i += 256) {
        int t = i >> 5, d = i & 31;
        qs[d * 68 + t] = g_q[base + i];
        ks[d * 68 + t] = g_k[base + i];
        vs[i]          = g_v[base + i];
    }
    for (int i = tid; i < 225; i += 256) rb[i] = rpb[i * 6 + head];
    __syncthreads();

    const int tx = tid & 15, ty = tid >> 4;
    const int m0 = ty * 4, n0 = tx * 4;
    float acc[4][4] = {};
    #pragma unroll
    for (int d = 0; d < 32; d++) {
        float4 a  = *(const float4*)(qs + d * 68 + m0);
        float4 bv = *(const float4*)(ks + d * 68 + n0);
        acc[0][0] += a.x * bv.x; acc[0][1] += a.x * bv.y; acc[0][2] += a.x * bv.z; acc[0][3] += a.x * bv.w;
        acc[1][0] += a.y * bv.x; acc[1][1] += a.y * bv.y; acc[1][2] += a.y * bv.z; acc[1][3] += a.y * bv.w;
        acc[2][0] += a.z * bv.x; acc[2][1] += a.z * bv.y; acc[2][2] += a.z * bv.z; acc[2][3] += a.z * bv.w;
        acc[3][0] += a.w * bv.x; acc[3][1] += a.w * bv.y; acc[3][2] += a.w * bv.z; acc[3][3] += a.w * bv.w;
    }

    int lq[4], lk[4];
    #pragma unroll
    for (int i = 0; i < 4; i++) {
        int m = m0 + i; int ti = m >> 3, tj = m & 7;
        lq[i] = ((wh == 31) ? ((ti < 4) ? 1 : 2) : 0) * 3
              + ((wc == 31) ? ((tj < 4) ? 1 : 2) : 0);
        int n = n0 + i; int ki = n >> 3, kj = n & 7;
        lk[i] = ((wh == 31) ? ((ki < 4) ? 1 : 2) : 0) * 3
              + ((wc == 31) ? ((kj < 4) ? 1 : 2) : 0);
    }
    #pragma unroll
    for (int i = 0; i < 4; i++) {
        int m = m0 + i;
        #pragma unroll
        for (int j = 0; j < 4; j++) {
            int n = n0 + j;
            int rel = ((m >> 3) - (n >> 3) + 7) * 15 + ((m & 7) - (n & 7) + 7);
            float v = acc[i][j] + rb[rel];
            if (lq[i] != lk[j]) v -= 100.0f;
            ss[m * 68 + n] = v;
        }
    }
    __syncthreads();   // scores complete; qs/ks dead from here

    {
        const int row = tid >> 2, l4 = tid & 3;
        float vals[16];
        float mx = -1e30f;
        #pragma unroll
        for (int t = 0; t < 16; t++) {
            vals[t] = ss[row * 68 + l4 + 4 * t];
            mx = fmaxf(mx, vals[t]);
        }
        mx = fmaxf(mx, __shfl_xor_sync(0xffffffffu, mx, 1));
        mx = fmaxf(mx, __shfl_xor_sync(0xffffffffu, mx, 2));
        float sum = 0.f;
        #pragma unroll
        for (int t = 0; t < 16; t++) { vals[t] = __expf(vals[t] - mx); sum += vals[t]; }
        sum += __shfl_xor_sync(0xffffffffu, sum, 1);
        sum += __shfl_xor_sync(0xffffffffu, sum, 2);
        float inv = 1.0f / sum;
        #pragma unroll
        for (int t = 0; t < 16; t++) st[(l4 + 4 * t) * 68 + row] = vals[t] * inv;
    }
    __syncthreads();

    {
        const int kh = tid >> 7;
        const int rem = tid & 127;
        const int pm0 = (rem >> 3) * 4;
        const int pn0 = (rem & 7) * 4;
        float o[4][4] = {};
        const int k0 = kh * 32;
        #pragma unroll 8
        for (int k = k0; k < k0 + 32; k++) {
            float4 a = *(const float4*)(st + k * 68 + pm0);
            float4 b = *(const float4*)(vs + k * 32 + pn0);
            o[0][0] += a.x * b.x; o[0][1] += a.x * b.y; o[0][2] += a.x * b.z; o[0][3] += a.x * b.w;
            o[1][0] += a.y * b.x; o[1][1] += a.y * b.y; o[1][2] += a.y * b.z; o[1][3] += a.y * b.w;
            o[2][0] += a.z * b.x; o[2][1] += a.z * b.y; o[2][2] += a.z * b.z; o[2][3] += a.z * b.w;
            o[3][0] += a.w * b.x; o[3][1] += a.w * b.y; o[3][2] += a.w * b.z; o[3][3] += a.w * b.w;
        }
        __syncthreads();
        #pragma unroll
        for (int i = 0; i < 4; i++)
            *(float4*)&ss[kh * 2048 + (pm0 + i) * 32 + pn0] =
                make_float4(o[i][0], o[i][1], o[i][2], o[i][3]);
    }
    __syncthreads();

    {
        const int j = tid * 8;
        const int m = j >> 5, n = j & 31;
        float4 p0 = *(const float4*)&ss[m * 32 + n];
        float4 p1 = *(const float4*)&ss[m * 32 + n + 4];
        float4 q0 = *(const float4*)&ss[2048 + m * 32 + n];
        float4 q1 = *(const float4*)&ss[2048 + m * 32 + n + 4];
        p0.x += q0.x; p0.y += q0.y; p0.z += q0.z; p0.w += q0.w;
        p1.x += q1.x; p1.y += q1.y; p1.z += q1.z; p1.w += q1.w;
        float* dst = &g_ao[(win * 64 + m) * DIM + head * 32 + n];
        *(float4*)dst = p0;
        *(float4*)(dst + 4) = p1;
    }
}

// ---------------- launch ------------------------------------------------------
extern "C" void kernel_launch(void* const* d_in, const int* in_sizes, int n_in,
                              void* d_out, int out_size) {
    const float* x      = (const float*)d_in[0];
    const float* qkv_w  = (const float*)d_in[1];
    const float* qkv_b  = (const float*)d_in[2];
    const float* proj_w = (const float*)d_in[3];
    const float* proj_b = (const float*)d_in[4];
    const float* rpb    = (const float*)d_in[5];
    float* out = (float*)d_out;

    cudaFuncSetAttribute(qkv_mma_kernel,  cudaFuncAttributeMaxDynamicSharedMemorySize, SM_BYTES);
    cudaFuncSetAttribute(proj_mma_kernel, cudaFuncAttributeMaxDynamicSharedMemorySize, SM_BYTES);

    prep_bq_kernel<<<(576 * 192 + 255) / 256, 256>>>(qkv_w);
    prep_bp_kernel<<<(192 * 192 + 255) / 256, 256>>>(proj_w);
    qkv_mma_kernel<<<NWIN, 256, SM_BYTES>>>(x, qkv_b);
    attn_kernel<<<NWIN * HEADS, 256>>>(rpb);
    proj_mma_kernel<<<NWIN, 256, SM_BYTES>>>(proj_b, out);
}

// round 10
// speedup vs baseline: 1.5644x; 1.5644x over previous
#include <cuda_runtime.h>
#include <cuda_bf16.h>
#include <cstdint>

// ---------------------------------------------------------------------------
// Swin shifted-window attention, GB300 (compute_103: tensor pipe via mma.sync).
//   B=4, DIM=192, HEADS=6, HD=32, H=W=256, WS=8, SS=4 -> 4096 windows x 64 tok
// Round-9:
//   - qkv/proj GEMMs: M=128/CTA (2 windows). A (hi/lo bf16) in smem (102.4KB
//     -> 2 CTAs/SM). B is PRE-PACKED in mma-fragment order in gmem and loaded
//     with one coalesced LDG.64 per n8-tile per k-step (L1/L2 resident).
//     NO syncthreads in the tile loop, no B smem, no mbarriers.
//   - attention: round-6 fp32 SIMT kernel verbatim (passed at 477us).
// Split precision: C = Ah*Bh + Al*Bh + Ah*Bl  (error ~7e-6 << 1e-3 gate)
// ---------------------------------------------------------------------------

#define DIM    192
#define HEADS  6
#define SHIFT  4
#define NWIN   4096
#define QSCALE 0.17677669529663687f

#define LDA 200              // bf16 elems per A row (400B pitch: 8 distinct
                             // bank phases across ldmatrix's 8 rows -> clean)
#define AH_B 0               // Ah [128][200] bf16 (51200 B)
#define AL_B 51200           // Al [128][200]
#define SM_BYTES 102400      // 2 CTAs/SM

// ---------------- scratch ---------------------------------------------------
// B packed in canonical m16n8k16 B-fragment order:
//   index = ((nt*8 + j8)*36 + ks)*32 + lane   (uint2 = {b0,b1} for that lane)
//   ks = s*12 + k16; segments s0=Ah*Bh, s1=Al*Bh, s2=Ah*Bl (B half baked in)
__device__ uint2 g_bqf[9 * 8 * 36 * 32];          // qkv_w packed (663KB)
__device__ uint2 g_bpf[3 * 8 * 36 * 32];          // proj_w packed (221KB)
__device__ float g_q[NWIN * HEADS * 64 * 32];     // [win][head][t][d] (scaled)
__device__ float g_k[NWIN * HEADS * 64 * 32];
__device__ float g_v[NWIN * HEADS * 64 * 32];
__device__ float g_ao[NWIN * 64 * DIM];           // [win][t][c]

// ---------------- helpers ---------------------------------------------------
__device__ __forceinline__ uint32_t smem_u32(const void* p) {
    uint32_t a;
    asm("{ .reg .u64 t; cvta.to.shared.u64 t, %1; cvt.u32.u64 %0, t; }" : "=r"(a) : "l"(p));
    return a;
}
__device__ __forceinline__ void ldm_x4(uint32_t addr, uint32_t* r) {
    asm volatile("ldmatrix.sync.aligned.m8n8.x4.shared.b16 {%0,%1,%2,%3}, [%4];"
                 : "=r"(r[0]), "=r"(r[1]), "=r"(r[2]), "=r"(r[3]) : "r"(addr));
}
__device__ __forceinline__ void mma16816(float* acc, const uint32_t* a, uint32_t b0, uint32_t b1) {
    asm volatile("mma.sync.aligned.m16n8k16.row.col.f32.bf16.bf16.f32 "
                 "{%0,%1,%2,%3}, {%4,%5,%6,%7}, {%8,%9}, {%0,%1,%2,%3};"
                 : "+f"(acc[0]), "+f"(acc[1]), "+f"(acc[2]), "+f"(acc[3])
                 : "r"(a[0]), "r"(a[1]), "r"(a[2]), "r"(a[3]), "r"(b0), "r"(b1));
}

__device__ __forceinline__ uint32_t pack_bf16_pair(const float* __restrict__ w,
                                                   int n, int k, int ldw, bool lo) {
    float f0 = w[n * ldw + k], f1 = w[n * ldw + k + 1];
    __nv_bfloat16 h0 = __float2bfloat16(f0), h1 = __float2bfloat16(f1);
    if (lo) {
        h0 = __float2bfloat16(f0 - __bfloat162float(h0));
        h1 = __float2bfloat16(f1 - __bfloat162float(h1));
    }
    return ((uint32_t)__bfloat16_as_ushort(h1) << 16) | (uint32_t)__bfloat16_as_ushort(h0);
}

// ---------------- B fragment-pack prep ---------------------------------------
// lane l of warp holds b0 = B[n = base+l/4][k = k16*16 + 2*(l%4)] (+1 in high),
//                      b1 = same with k+8.  (canonical m16n8k16 .col B layout)
__global__ void prep_bqf_kernel(const float* __restrict__ w) {   // [576][192]
    int i = blockIdx.x * 256 + threadIdx.x;
    if (i >= 9 * 8 * 36 * 32) return;
    int lane = i & 31;
    int ks   = (i >> 5) % 36;
    int jt   = (i >> 5) / 36;                 // nt*8 + j8  (0..71)
    int s = ks / 12, k16 = ks - s * 12;
    bool lo = (s == 2);
    int n  = jt * 8 + (lane >> 2);            // = nt*64 + j8*8 + lane/4
    int kk = k16 * 16 + (lane & 3) * 2;
    uint2 v;
    v.x = pack_bf16_pair(w, n, kk,     192, lo);
    v.y = pack_bf16_pair(w, n, kk + 8, 192, lo);
    g_bqf[i] = v;
}
__global__ void prep_bpf_kernel(const float* __restrict__ w) {   // [192][192]
    int i = blockIdx.x * 256 + threadIdx.x;
    if (i >= 3 * 8 * 36 * 32) return;
    int lane = i & 31;
    int ks   = (i >> 5) % 36;
    int jt   = (i >> 5) / 36;
    int s = ks / 12, k16 = ks - s * 12;
    bool lo = (s == 2);
    int n  = jt * 8 + (lane >> 2);
    int kk = k16 * 16 + (lane & 3) * 2;
    uint2 v;
    v.x = pack_bf16_pair(w, n, kk,     192, lo);
    v.y = pack_bf16_pair(w, n, kk + 8, 192, lo);
    g_bpf[i] = v;
}

// ---------------- split-K mainloop (A smem + packed-B gmem) ------------------
// Warp computes a 32x32 tile: acc[i][j], i = 16-row half, j = n8 quarter.
__device__ __forceinline__ void gemm_tile(uint32_t sb, const uint2* __restrict__ bw,
                                          int wm, int lane, float acc[2][4][4]) {
    const int sub = lane >> 3, r8 = lane & 7;
    const int arow0 = wm * 32 + ((sub & 1) << 3) + r8;
    const int akoff = (sub >> 1) << 3;

    #pragma unroll
    for (int s = 0; s < 3; s++) {
        const uint32_t Ab = sb + ((s == 1) ? AL_B : AH_B)
                          + (uint32_t)(arow0 * LDA + akoff) * 2;
        #pragma unroll
        for (int k16 = 0; k16 < 12; k16++) {
            const int ks = s * 12 + k16;
            uint2 b[4];
            #pragma unroll
            for (int j = 0; j < 4; j++)
                b[j] = __ldg(bw + (j * 36 + ks) * 32 + lane);
            uint32_t a0[4], a1[4];
            ldm_x4(Ab + k16 * 32, a0);
            ldm_x4(Ab + 16 * LDA * 2 + k16 * 32, a1);
            #pragma unroll
            for (int j = 0; j < 4; j++) {
                mma16816(acc[0][j], a0, b[j].x, b[j].y);
                mma16816(acc[1][j], a1, b[j].x, b[j].y);
            }
        }
    }
}

// ---------------- QKV GEMM ---------------------------------------------------
__global__ __launch_bounds__(256, 2)
void qkv_mma_kernel(const float* __restrict__ x, const float* __restrict__ qkv_b) {
    extern __shared__ __align__(16) __nv_bfloat16 sm[];
    __nv_bfloat16* Ah = sm;                 // [128][200]
    __nv_bfloat16* Al = sm + 25600;
    const uint32_t sb = smem_u32(sm);

    const int tid = threadIdx.x;
    const int warp = tid >> 5, lane = tid & 31;
    const int wm = warp >> 1, wn = warp & 1;
    const int win0 = blockIdx.x * 2;

    // gather shifted-window x -> Ah/Al  (2 windows = 128 rows x 192 ch)
    for (int idx = tid; idx < 192 * 128; idx += 256) {
        int k = idx >> 7, r = idx & 127;
        int win = win0 + (r >> 6), t = r & 63;
        int wi = win & 1023, wh = wi >> 5, wc = wi & 31, bb = win >> 10;
        int h = (wh * 8 + (t >> 3) + SHIFT) & 255;
        int w = (wc * 8 + (t & 7) + SHIFT) & 255;
        float f = x[(bb * 192 + k) * 65536 + (h << 8) + w];
        __nv_bfloat16 hi = __float2bfloat16(f);
        Ah[r * LDA + k] = hi;
        Al[r * LDA + k] = __float2bfloat16(f - __bfloat162float(hi));
    }
    __syncthreads();          // the ONLY block-wide sync

    for (int nt = 0; nt < 9; nt++) {
        float acc[2][4][4];
        #pragma unroll
        for (int i = 0; i < 2; i++)
            #pragma unroll
            for (int j = 0; j < 4; j++)
                acc[i][j][0] = acc[i][j][1] = acc[i][j][2] = acc[i][j][3] = 0.f;

        const uint2* bw = g_bqf + (size_t)(nt * 8 + wn * 4) * 36 * 32;
        gemm_tile(sb, bw, wm, lane, acc);

        const int sel = nt / 3;               // 0=q 1=k 2=v
        float* dst = (sel == 0) ? g_q : ((sel == 1) ? g_k : g_v);
        const int r0 = wm * 32 + (lane >> 2);
        #pragma unroll
        for (int i = 0; i < 2; i++) {
            #pragma unroll
            for (int j = 0; j < 4; j++) {
                int n  = nt * 64 + wn * 32 + j * 8 + 2 * (lane & 3);
                int nn = n - sel * 192;
                int head = nn >> 5, d = nn & 31;
                float b0 = __ldg(qkv_b + n), b1 = __ldg(qkv_b + n + 1);
                #pragma unroll
                for (int half = 0; half < 2; half++) {
                    int row = r0 + i * 16 + half * 8;
                    int win = win0 + (row >> 6), t = row & 63;
                    float v0 = acc[i][j][half * 2 + 0] + b0;
                    float v1 = acc[i][j][half * 2 + 1] + b1;
                    if (sel == 0) { v0 *= QSCALE; v1 *= QSCALE; }
                    *(float2*)&dst[((win * 6 + head) * 64 + t) * 32 + d] = make_float2(v0, v1);
                }
            }
        }
    }
}

// ---------------- proj GEMM --------------------------------------------------
__global__ __launch_bounds__(256, 2)
void proj_mma_kernel(const float* __restrict__ proj_b, float* __restrict__ out) {
    extern __shared__ __align__(16) __nv_bfloat16 sm[];
    __nv_bfloat16* Ah = sm;
    __nv_bfloat16* Al = sm + 25600;
    const uint32_t sb = smem_u32(sm);

    const int tid = threadIdx.x;
    const int warp = tid >> 5, lane = tid & 31;
    const int wm = warp >> 1, wn = warp & 1;
    const int win0 = blockIdx.x * 2;

    const float* ao = g_ao + (size_t)win0 * (64 * DIM);
    for (int idx = tid; idx < 192 * 128; idx += 256) {
        int r = idx / 192, k = idx - r * 192;   // coalesced gmem read
        float f = ao[idx];
        __nv_bfloat16 hi = __float2bfloat16(f);
        Ah[r * LDA + k] = hi;
        Al[r * LDA + k] = __float2bfloat16(f - __bfloat162float(hi));
    }
    __syncthreads();

    for (int nt = 0; nt < 3; nt++) {
        float acc[2][4][4];
        #pragma unroll
        for (int i = 0; i < 2; i++)
            #pragma unroll
            for (int j = 0; j < 4; j++)
                acc[i][j][0] = acc[i][j][1] = acc[i][j][2] = acc[i][j][3] = 0.f;

        const uint2* bw = g_bpf + (size_t)(nt * 8 + wn * 4) * 36 * 32;
        gemm_tile(sb, bw, wm, lane, acc);

        const int r0 = wm * 32 + (lane >> 2);
        #pragma unroll
        for (int i = 0; i < 2; i++) {
            #pragma unroll
            for (int j = 0; j < 4; j++) {
                int c = nt * 64 + wn * 32 + j * 8 + 2 * (lane & 3);
                float b0 = __ldg(proj_b + c), b1 = __ldg(proj_b + c + 1);
                #pragma unroll
                for (int half = 0; half < 2; half++) {
                    int row = r0 + i * 16 + half * 8;
                    int win = win0 + (row >> 6), t = row & 63;
                    int wi = win & 1023, wh = wi >> 5, wc = wi & 31, bb = win >> 10;
                    int h = (wh * 8 + (t >> 3) + SHIFT) & 255;   // reverse shift
                    int w = (wc * 8 + (t & 7) + SHIFT) & 255;
                    int pix = (h << 8) + w;
                    out[(bb * 192 + c) * 65536 + pix]     = acc[i][j][half * 2 + 0] + b0;
                    out[(bb * 192 + c + 1) * 65536 + pix] = acc[i][j][half * 2 + 1] + b1;
                }
            }
        }
    }
}

// ---------------- attention (fp32 SIMT, round-6 version) ---------------------
__global__ __launch_bounds__(256, 4)
void attn_kernel(const float* __restrict__ rpb) {
    __shared__ __align__(16) float qk[2 * 32 * 68];  // qs|ks, later P^T [k][q]
    __shared__ __align__(16) float vs[64 * 32];      // v [k][d]
    __shared__ __align__(16) float ss[64 * 68];      // scores, later partials
    __shared__ float rb[225];
    float* qs = qk;
    float* ks = qk + 32 * 68;
    float* st = qk;                                   // P^T overlay [64][68]

    const int bid  = blockIdx.x;
    const int win  = bid / 6;
    const int head = bid - win * 6;
    const int wi   = win & 1023;
    const int wh   = wi >> 5;
    const int wc   = wi & 31;
    const int tid  = threadIdx.x;

    const int base = (win * HEADS + head) * 64 * 32;
    for (int i = tid; i < 64 * 32; i += 256) {
        int t = i >> 5, d = i & 31;
        qs[d * 68 + t] = g_q[base + i];
        ks[d * 68 + t] = g_k[base + i];
        vs[i]          = g_v[base + i];
    }
    for (int i = tid; i < 225; i += 256) rb[i] = rpb[i * 6 + head];
    __syncthreads();

    const int tx = tid & 15, ty = tid >> 4;
    const int m0 = ty * 4, n0 = tx * 4;
    float acc[4][4] = {};
    #pragma unroll
    for (int d = 0; d < 32; d++) {
        float4 a  = *(const float4*)(qs + d * 68 + m0);
        float4 bv = *(const float4*)(ks + d * 68 + n0);
        acc[0][0] += a.x * bv.x; acc[0][1] += a.x * bv.y; acc[0][2] += a.x * bv.z; acc[0][3] += a.x * bv.w;
        acc[1][0] += a.y * bv.x; acc[1][1] += a.y * bv.y; acc[1][2] += a.y * bv.z; acc[1][3] += a.y * bv.w;
        acc[2][0] += a.z * bv.x; acc[2][1] += a.z * bv.y; acc[2][2] += a.z * bv.z; acc[2][3] += a.z * bv.w;
        acc[3][0] += a.w * bv.x; acc[3][1] += a.w * bv.y; acc[3][2] += a.w * bv.z; acc[3][3] += a.w * bv.w;
    }

    int lq[4], lk[4];
    #pragma unroll
    for (int i = 0; i < 4; i++) {
        int m = m0 + i; int ti = m >> 3, tj = m & 7;
        lq[i] = ((wh == 31) ? ((ti < 4) ? 1 : 2) : 0) * 3
              + ((wc == 31) ? ((tj < 4) ? 1 : 2) : 0);
        int n = n0 + i; int ki = n >> 3, kj = n & 7;
        lk[i] = ((wh == 31) ? ((ki < 4) ? 1 : 2) : 0) * 3
              + ((wc == 31) ? ((kj < 4) ? 1 : 2) : 0);
    }
    #pragma unroll
    for (int i = 0; i < 4; i++) {
        int m = m0 + i;
        #pragma unroll
        for (int j = 0; j < 4; j++) {
            int n = n0 + j;
            int rel = ((m >> 3) - (n >> 3) + 7) * 15 + ((m & 7) - (n & 7) + 7);
            float v = acc[i][j] + rb[rel];
            if (lq[i] != lk[j]) v -= 100.0f;
            ss[m * 68 + n] = v;
        }
    }
    __syncthreads();   // scores complete; qs/ks dead from here

    {
        const int row = tid >> 2, l4 = tid & 3;
        float vals[16];
        float mx = -1e30f;
        #pragma unroll
        for (int t = 0; t < 16; t++) {
            vals[t] = ss[row * 68 + l4 + 4 * t];
            mx = fmaxf(mx, vals[t]);
        }
        mx = fmaxf(mx, __shfl_xor_sync(0xffffffffu, mx, 1));
        mx = fmaxf(mx, __shfl_xor_sync(0xffffffffu, mx, 2));
        float sum = 0.f;
        #pragma unroll
        for (int t = 0; t < 16; t++) { vals[t] = __expf(vals[t] - mx); sum += vals[t]; }
        sum += __shfl_xor_sync(0xffffffffu, sum, 1);
        sum += __shfl_xor_sync(0xffffffffu, sum, 2);
        float inv = 1.0f / sum;
        #pragma unroll
        for (int t = 0; t < 16; t++) st[(l4 + 4 * t) * 68 + row] = vals[t] * inv;
    }
    __syncthreads();

    {
        const int kh = tid >> 7;
        const int rem = tid & 127;
        const int pm0 = (rem >> 3) * 4;
        const int pn0 = (rem & 7) * 4;
        float o[4][4] = {};
        const int k0 = kh * 32;
        #pragma unroll 8
        for (int k = k0; k < k0 + 32; k++) {
            float4 a = *(const float4*)(st + k * 68 + pm0);
            float4 b = *(const float4*)(vs + k * 32 + pn0);
            o[0][0] += a.x * b.x; o[0][1] += a.x * b.y; o[0][2] += a.x * b.z; o[0][3] += a.x * b.w;
            o[1][0] += a.y * b.x; o[1][1] += a.y * b.y; o[1][2] += a.y * b.z; o[1][3] += a.y * b.w;
            o[2][0] += a.z * b.x; o[2][1] += a.z * b.y; o[2][2] += a.z * b.z; o[2][3] += a.z * b.w;
            o[3][0] += a.w * b.x; o[3][1] += a.w * b.y; o[3][2] += a.w * b.z; o[3][3] += a.w * b.w;
        }
        __syncthreads();
        #pragma unroll
        for (int i = 0; i < 4; i++)
            *(float4*)&ss[kh * 2048 + (pm0 + i) * 32 + pn0] =
                make_float4(o[i][0], o[i][1], o[i][2], o[i][3]);
    }
    __syncthreads();

    {
        const int j = tid * 8;
        const int m = j >> 5, n = j & 31;
        float4 p0 = *(const float4*)&ss[m * 32 + n];
        float4 p1 = *(const float4*)&ss[m * 32 + n + 4];
        float4 q0 = *(const float4*)&ss[2048 + m * 32 + n];
        float4 q1 = *(const float4*)&ss[2048 + m * 32 + n + 4];
        p0.x += q0.x; p0.y += q0.y; p0.z += q0.z; p0.w += q0.w;
        p1.x += q1.x; p1.y += q1.y; p1.z += q1.z; p1.w += q1.w;
        float* dst = &g_ao[(win * 64 + m) * DIM + head * 32 + n];
        *(float4*)dst = p0;
        *(float4*)(dst + 4) = p1;
    }
}

// ---------------- launch ------------------------------------------------------
extern "C" void kernel_launch(void* const* d_in, const int* in_sizes, int n_in,
                              void* d_out, int out_size) {
    const float* x      = (const float*)d_in[0];
    const float* qkv_w  = (const float*)d_in[1];
    const float* qkv_b  = (const float*)d_in[2];
    const float* proj_w = (const float*)d_in[3];
    const float* proj_b = (const float*)d_in[4];
    const float* rpb    = (const float*)d_in[5];
    float* out = (float*)d_out;

    cudaFuncSetAttribute(qkv_mma_kernel,  cudaFuncAttributeMaxDynamicSharedMemorySize, SM_BYTES);
    cudaFuncSetAttribute(proj_mma_kernel, cudaFuncAttributeMaxDynamicSharedMemorySize, SM_BYTES);

    prep_bqf_kernel<<<(9 * 8 * 36 * 32 + 255) / 256, 256>>>(qkv_w);
    prep_bpf_kernel<<<(3 * 8 * 36 * 32 + 255) / 256, 256>>>(proj_w);
    qkv_mma_kernel<<<NWIN / 2, 256, SM_BYTES>>>(x, qkv_b);
    attn_kernel<<<NWIN * HEADS, 256>>>(rpb);
    proj_mma_kernel<<<NWIN / 2, 256, SM_BYTES>>>(proj_b, out);
}

// round 12
// speedup vs baseline: 1.7249x; 1.1026x over previous
#include <cuda_runtime.h>
#include <cuda_bf16.h>
#include <cstdint>

// ---------------------------------------------------------------------------
// Swin shifted-window attention, GB300 (compute_103: tensor pipe via mma.sync).
//   B=4, DIM=192, HEADS=6, HD=32, H=W=256, WS=8, SS=4 -> 4096 windows x 64 tok
// Round-11 (= round-6 + register-pipelined GEMM mainloop):
//   - qkv/proj GEMMs: bf16 split-K (C = Ah*Bh + Al*Bh + Ah*Bl), M=128/CTA,
//     cp.async double-buffered B staging, and a flattened 36-step mainloop
//     with REGISTER double-buffered fragments (prefetch k+1 before mma k)
//     to hide ldmatrix->mma RAW latency at 8 warps/SM.
//   - attention: round-6 fp32 SIMT kernel verbatim (477us, stable).
// ---------------------------------------------------------------------------

#define DIM    192
#define HEADS  6
#define SHIFT  4
#define NWIN   4096
#define QSCALE 0.17677669529663687f

#define LDA 200              // bf16 elems per A row (400B pitch, conflict-free)
#define LDB 200
// smem byte offsets
#define AH_B 0               // Ah [128][200]
#define AL_B 51200           // Al [128][200]
#define B0_B 102400          // buf0: Bh | Bl (25600 each)
#define B1_B 153600          // buf1: Bh | Bl
#define SM_BYTES 204800

// ---------------- scratch ---------------------------------------------------
__device__ __nv_bfloat16 g_bq[576 * 384];         // qkv_w  hi|lo per row
__device__ __nv_bfloat16 g_bp[192 * 384];         // proj_w hi|lo per row
__device__ float g_q[NWIN * HEADS * 64 * 32];     // [win][head][t][d] (scaled)
__device__ float g_k[NWIN * HEADS * 64 * 32];
__device__ float g_v[NWIN * HEADS * 64 * 32];
__device__ float g_ao[NWIN * 64 * DIM];           // [win][t][c]

// ---------------- helpers ---------------------------------------------------
__device__ __forceinline__ uint32_t smem_u32(const void* p) {
    uint32_t a;
    asm("{ .reg .u64 t; cvta.to.shared.u64 t, %1; cvt.u32.u64 %0, t; }" : "=r"(a) : "l"(p));
    return a;
}
__device__ __forceinline__ void ldm_x4(uint32_t addr, uint32_t* r) {
    asm volatile("ldmatrix.sync.aligned.m8n8.x4.shared.b16 {%0,%1,%2,%3}, [%4];"
                 : "=r"(r[0]), "=r"(r[1]), "=r"(r[2]), "=r"(r[3]) : "r"(addr));
}
__device__ __forceinline__ void mma16816(float* acc, const uint32_t* a, uint32_t b0, uint32_t b1) {
    asm volatile("mma.sync.aligned.m16n8k16.row.col.f32.bf16.bf16.f32 "
                 "{%0,%1,%2,%3}, {%4,%5,%6,%7}, {%8,%9}, {%0,%1,%2,%3};"
                 : "+f"(acc[0]), "+f"(acc[1]), "+f"(acc[2]), "+f"(acc[3])
                 : "r"(a[0]), "r"(a[1]), "r"(a[2]), "r"(a[3]), "r"(b0), "r"(b1));
}
#define CP_ASYNC16(dst, src) \
    asm volatile("cp.async.cg.shared.global [%0], [%1], 16;" :: "r"(dst), "l"(src))
#define CP_COMMIT()  asm volatile("cp.async.commit_group;" ::: "memory")
#define CP_WAIT(N)   asm volatile("cp.async.wait_group %0;" :: "n"(N) : "memory")

// fragment load for flattened step ks (0..35):
//   ks in [0,12): Ah*Bh   [12,24): Al*Bh   [24,36): Ah*Bl
__device__ __forceinline__ void load_frags(uint32_t sb, uint32_t bh_off, int ks,
                                           uint32_t aoff, uint32_t boff,
                                           uint32_t* a0, uint32_t* a1,
                                           uint32_t* p, uint32_t* q) {
    const int k16 = ks % 12;
    const uint32_t Ab = sb + ((ks >= 12 && ks < 24) ? AL_B : AH_B) + aoff + k16 * 32;
    const uint32_t Bb = sb + bh_off + ((ks >= 24) ? 25600u : 0u) + boff + k16 * 32;
    ldm_x4(Ab, a0);
    ldm_x4(Ab + 16 * LDA * 2, a1);
    ldm_x4(Bb, p);
    ldm_x4(Bb + 16 * LDB * 2, q);
}

// 36-step split-K mainloop, register double-buffered (prefetch depth 1).
__device__ __forceinline__ void gemm_split(uint32_t sb, uint32_t bh_off,
                                           int wm, int wn, int lane,
                                           float acc[2][4][4]) {
    const int sub = lane >> 3, r8 = lane & 7;
    const uint32_t aoff = (uint32_t)((wm * 32 + ((sub & 1) << 3) + r8) * LDA
                                     + (((sub >> 1) << 3))) * 2;
    const uint32_t boff = (uint32_t)((wn * 32 + ((sub >> 1) << 3) + r8) * LDB
                                     + (((sub & 1) << 3))) * 2;

    uint32_t a0[2][4], a1[2][4], p[2][4], q[2][4];
    load_frags(sb, bh_off, 0, aoff, boff, a0[0], a1[0], p[0], q[0]);

    #pragma unroll
    for (int ks = 0; ks < 36; ks++) {
        const int cur = ks & 1, nxt = cur ^ 1;
        if (ks < 35)
            load_frags(sb, bh_off, ks + 1, aoff, boff, a0[nxt], a1[nxt], p[nxt], q[nxt]);
        mma16816(acc[0][0], a0[cur], p[cur][0], p[cur][1]);
        mma16816(acc[0][1], a0[cur], p[cur][2], p[cur][3]);
        mma16816(acc[0][2], a0[cur], q[cur][0], q[cur][1]);
        mma16816(acc[0][3], a0[cur], q[cur][2], q[cur][3]);
        mma16816(acc[1][0], a1[cur], p[cur][0], p[cur][1]);
        mma16816(acc[1][1], a1[cur], p[cur][2], p[cur][3]);
        mma16816(acc[1][2], a1[cur], q[cur][0], q[cur][1]);
        mma16816(acc[1][3], a1[cur], q[cur][2], q[cur][3]);
    }
}

// stage one 64-row B tile (hi+lo) into buffer via cp.async
__device__ __forceinline__ void stage_B(uint32_t sb, uint32_t buf_off,
                                        const __nv_bfloat16* wsplit,
                                        int nt, int tid) {
    const char* src_base = (const char*)wsplit + (size_t)nt * 64 * 768;
    #pragma unroll
    for (int u = 0; u < 12; u++) {
        int idx = tid + u * 256;              // 3072 chunks of 16B
        int n = idx / 48, rem = idx - n * 48;
        int half = rem / 24;                  // 0 = hi, 1 = lo
        int c = rem - half * 24;
        uint32_t dst = sb + buf_off + (uint32_t)half * 25600 + (uint32_t)(n * 400 + c * 16);
        const char* src = src_base + n * 768 + half * 384 + c * 16;
        CP_ASYNC16(dst, src);
    }
}

// ---------------- weight split prep -----------------------------------------
__global__ void prep_bq_kernel(const float* __restrict__ w) {   // [576][192]
    int i = blockIdx.x * 256 + threadIdx.x;
    if (i < 576 * 192) {
        int n = i / 192, k = i - n * 192;
        float f = w[i];
        __nv_bfloat16 hi = __float2bfloat16(f);
        g_bq[n * 384 + k]       = hi;
        g_bq[n * 384 + 192 + k] = __float2bfloat16(f - __bfloat162float(hi));
    }
}
__global__ void prep_bp_kernel(const float* __restrict__ w) {   // [192][192]
    int i = blockIdx.x * 256 + threadIdx.x;
    if (i < 192 * 192) {
        int n = i / 192, k = i - n * 192;
        float f = w[i];
        __nv_bfloat16 hi = __float2bfloat16(f);
        g_bp[n * 384 + k]       = hi;
        g_bp[n * 384 + 192 + k] = __float2bfloat16(f - __bfloat162float(hi));
    }
}

// ---------------- QKV GEMM (mma.sync, double-buffered B) ---------------------
__global__ __launch_bounds__(256, 1)
void qkv_mma_kernel(const float* __restrict__ x, const float* __restrict__ qkv_b) {
    extern __shared__ __align__(16) __nv_bfloat16 sm[];
    __nv_bfloat16* Ah = sm;
    __nv_bfloat16* Al = sm + 25600;
    const uint32_t sb = smem_u32(sm);

    const int tid = threadIdx.x;
    const int warp = tid >> 5, lane = tid & 31;
    const int wm = warp >> 1, wn = warp & 1;
    const int win0 = blockIdx.x * 2;

    // prefetch tile-0 B first so it overlaps the A gather
    stage_B(sb, B0_B, g_bq, 0, tid);
    CP_COMMIT();

    // gather shifted-window x -> Ah/Al
    for (int idx = tid; idx < 192 * 128; idx += 256) {
        int k = idx >> 7, r = idx & 127;
        int win = win0 + (r >> 6), t = r & 63;
        int wi = win & 1023, wh = wi >> 5, wc = wi & 31, bb = win >> 10;
        int h = (wh * 8 + (t >> 3) + SHIFT) & 255;
        int w = (wc * 8 + (t & 7) + SHIFT) & 255;
        float f = x[(bb * 192 + k) * 65536 + (h << 8) + w];
        __nv_bfloat16 hi = __float2bfloat16(f);
        Ah[r * LDA + k] = hi;
        Al[r * LDA + k] = __float2bfloat16(f - __bfloat162float(hi));
    }

    for (int nt = 0; nt < 9; nt++) {
        const uint32_t cur = (nt & 1) ? B1_B : B0_B;
        if (nt + 1 < 9) {
            stage_B(sb, (nt & 1) ? B0_B : B1_B, g_bq, nt + 1, tid);
            CP_COMMIT();
            CP_WAIT(1);                // current tile's group complete
        } else {
            CP_WAIT(0);
        }
        __syncthreads();               // B visible + A ready (first iter)

        float acc[2][4][4];
        #pragma unroll
        for (int i = 0; i < 2; i++)
            #pragma unroll
            for (int j = 0; j < 4; j++)
                acc[i][j][0] = acc[i][j][1] = acc[i][j][2] = acc[i][j][3] = 0.f;

        gemm_split(sb, cur, wm, wn, lane, acc);

        const int sel = nt / 3;               // 0=q 1=k 2=v
        float* dst = (sel == 0) ? g_q : ((sel == 1) ? g_k : g_v);
        const int r0 = wm * 32 + (lane >> 2);
        #pragma unroll
        for (int i = 0; i < 2; i++) {
            #pragma unroll
            for (int j = 0; j < 4; j++) {
                int n  = nt * 64 + wn * 32 + j * 8 + 2 * (lane & 3);
                int nn = n - sel * 192;
                int head = nn >> 5, d = nn & 31;
                float b0 = __ldg(qkv_b + n), b1 = __ldg(qkv_b + n + 1);
                #pragma unroll
                for (int half = 0; half < 2; half++) {
                    int row = r0 + i * 16 + half * 8;
                    int win = win0 + (row >> 6), t = row & 63;
                    float v0 = acc[i][j][half * 2 + 0] + b0;
                    float v1 = acc[i][j][half * 2 + 1] + b1;
                    if (sel == 0) { v0 *= QSCALE; v1 *= QSCALE; }
                    *(float2*)&dst[((win * 6 + head) * 64 + t) * 32 + d] = make_float2(v0, v1);
                }
            }
        }
        __syncthreads();               // done reading cur before it is re-staged
    }
}

// ---------------- attention (fp32 SIMT, transposed-P PV) ---------------------
__global__ __launch_bounds__(256, 4)
void attn_kernel(const float* __restrict__ rpb) {
    __shared__ __align__(16) float qk[2 * 32 * 68];  // qs|ks, later P^T [k][q]
    __shared__ __align__(16) float vs[64 * 32];      // v [k][d]
    __shared__ __align__(16) float ss[64 * 68];      // scores, later partials
    __shared__ float rb[225];
    float* qs = qk;
    float* ks = qk + 32 * 68;
    float* st = qk;                                   // P^T overlay [64][68]

    const int bid  = blockIdx.x;
    const int win  = bid / 6;
    const int head = bid - win * 6;
    const int wi   = win & 1023;
    const int wh   = wi >> 5;
    const int wc   = wi & 31;
    const int tid  = threadIdx.x;

    const int base = (win * HEADS + head) * 64 * 32;
    for (int i = tid; i < 64 * 32; i += 256) {
        int t = i >> 5, d = i & 31;
        qs[d * 68 + t] = g_q[base + i];
        ks[d * 68 + t] = g_k[base + i];
        vs[i]          = g_v[base + i];
    }
    for (int i = tid; i < 225; i += 256) rb[i] = rpb[i * 6 + head];
    __syncthreads();

    const int tx = tid & 15, ty = tid >> 4;
    const int m0 = ty * 4, n0 = tx * 4;
    float acc[4][4] = {};
    #pragma unroll
    for (int d = 0; d < 32; d++) {
        float4 a  = *(const float4*)(qs + d * 68 + m0);
        float4 bv = *(const float4*)(ks + d * 68 + n0);
        acc[0][0] += a.x * bv.x; acc[0][1] += a.x * bv.y; acc[0][2] += a.x * bv.z; acc[0][3] += a.x * bv.w;
        acc[1][0] += a.y * bv.x; acc[1][1] += a.y * bv.y; acc[1][2] += a.y * bv.z; acc[1][3] += a.y * bv.w;
        acc[2][0] += a.z * bv.x; acc[2][1] += a.z * bv.y; acc[2][2] += a.z * bv.z; acc[2][3] += a.z * bv.w;
        acc[3][0] += a.w * bv.x; acc[3][1] += a.w * bv.y; acc[3][2] += a.w * bv.z; acc[3][3] += a.w * bv.w;
    }

    int lq[4], lk[4];
    #pragma unroll
    for (int i = 0; i < 4; i++) {
        int m = m0 + i; int ti = m >> 3, tj = m & 7;
        lq[i] = ((wh == 31) ? ((ti < 4) ? 1 : 2) : 0) * 3
              + ((wc == 31) ? ((tj < 4) ? 1 : 2) : 0);
        int n = n0 + i; int ki = n >> 3, kj = n & 7;
        lk[i] = ((wh == 31) ? ((ki < 4) ? 1 : 2) : 0) * 3
              + ((wc == 31) ? ((kj < 4) ? 1 : 2) : 0);
    }
    #pragma unroll
    for (int i = 0; i < 4; i++) {
        int m = m0 + i;
        #pragma unroll
        for (int j = 0; j < 4; j++) {
            int n = n0 + j;
            int rel = ((m >> 3) - (n >> 3) + 7) * 15 + ((m & 7) - (n & 7) + 7);
            float v = acc[i][j] + rb[rel];
            if (lq[i] != lk[j]) v -= 100.0f;
            ss[m * 68 + n] = v;
        }
    }
    __syncthreads();   // scores complete; qs/ks dead from here

    {
        const int row = tid >> 2, l4 = tid & 3;
        float vals[16];
        float mx = -1e30f;
        #pragma unroll
        for (int t = 0; t < 16; t++) {
            vals[t] = ss[row * 68 + l4 + 4 * t];
            mx = fmaxf(mx, vals[t]);
        }
        mx = fmaxf(mx, __shfl_xor_sync(0xffffffffu, mx, 1));
        mx = fmaxf(mx, __shfl_xor_sync(0xffffffffu, mx, 2));
        float sum = 0.f;
        #pragma unroll
        for (int t = 0; t < 16; t++) { vals[t] = __expf(vals[t] - mx); sum += vals[t]; }
        sum += __shfl_xor_sync(0xffffffffu, sum, 1);
        sum += __shfl_xor_sync(0xffffffffu, sum, 2);
        float inv = 1.0f / sum;
        #pragma unroll
        for (int t = 0; t < 16; t++) st[(l4 + 4 * t) * 68 + row] = vals[t] * inv;
    }
    __syncthreads();

    {
        const int kh = tid >> 7;
        const int rem = tid & 127;
        const int pm0 = (rem >> 3) * 4;
        const int pn0 = (rem & 7) * 4;
        float o[4][4] = {};
        const int k0 = kh * 32;
        #pragma unroll 8
        for (int k = k0; k < k0 + 32; k++) {
            float4 a = *(const float4*)(st + k * 68 + pm0);
            float4 b = *(const float4*)(vs + k * 32 + pn0);
            o[0][0] += a.x * b.x; o[0][1] += a.x * b.y; o[0][2] += a.x * b.z; o[0][3] += a.x * b.w;
            o[1][0] += a.y * b.x; o[1][1] += a.y * b.y; o[1][2] += a.y * b.z; o[1][3] += a.y * b.w;
            o[2][0] += a.z * b.x; o[2][1] += a.z * b.y; o[2][2] += a.z * b.z; o[2][3] += a.z * b.w;
            o[3][0] += a.w * b.x; o[3][1] += a.w * b.y; o[3][2] += a.w * b.z; o[3][3] += a.w * b.w;
        }
        __syncthreads();
        #pragma unroll
        for (int i = 0; i < 4; i++)
            *(float4*)&ss[kh * 2048 + (pm0 + i) * 32 + pn0] =
                make_float4(o[i][0], o[i][1], o[i][2], o[i][3]);
    }
    __syncthreads();

    {
        const int j = tid * 8;
        const int m = j >> 5, n = j & 31;
        float4 p0 = *(const float4*)&ss[m * 32 + n];
        float4 p1 = *(const float4*)&ss[m * 32 + n + 4];
        float4 q0 = *(const float4*)&ss[2048 + m * 32 + n];
        float4 q1 = *(const float4*)&ss[2048 + m * 32 + n + 4];
        p0.x += q0.x; p0.y += q0.y; p0.z += q0.z; p0.w += q0.w;
        p1.x += q1.x; p1.y += q1.y; p1.z += q1.z; p1.w += q1.w;
        float* dst = &g_ao[(win * 64 + m) * DIM + head * 32 + n];
        *(float4*)dst = p0;
        *(float4*)(dst + 4) = p1;
    }
}

// ---------------- proj GEMM (mma.sync, double-buffered B) --------------------
__global__ __launch_bounds__(256, 1)
void proj_mma_kernel(const float* __restrict__ proj_b, float* __restrict__ out) {
    extern __shared__ __align__(16) __nv_bfloat16 sm[];
    __nv_bfloat16* Ah = sm;
    __nv_bfloat16* Al = sm + 25600;
    const uint32_t sb = smem_u32(sm);

    const int tid = threadIdx.x;
    const int warp = tid >> 5, lane = tid & 31;
    const int wm = warp >> 1, wn = warp & 1;
    const int win0 = blockIdx.x * 2;

    stage_B(sb, B0_B, g_bp, 0, tid);
    CP_COMMIT();

    const float* ao = g_ao + (size_t)win0 * (64 * DIM);
    for (int idx = tid; idx < 192 * 128; idx += 256) {
        int r = idx / 192, k = idx - r * 192;
        float f = ao[idx];
        __nv_bfloat16 hi = __float2bfloat16(f);
        Ah[r * LDA + k] = hi;
        Al[r * LDA + k] = __float2bfloat16(f - __bfloat162float(hi));
    }

    for (int nt = 0; nt < 3; nt++) {
        const uint32_t cur = (nt & 1) ? B1_B : B0_B;
        if (nt + 1 < 3) {
            stage_B(sb, (nt & 1) ? B0_B : B1_B, g_bp, nt + 1, tid);
            CP_COMMIT();
            CP_WAIT(1);
        } else {
            CP_WAIT(0);
        }
        __syncthreads();

        float acc[2][4][4];
        #pragma unroll
        for (int i = 0; i < 2; i++)
            #pragma unroll
            for (int j = 0; j < 4; j++)
                acc[i][j][0] = acc[i][j][1] = acc[i][j][2] = acc[i][j][3] = 0.f;

        gemm_split(sb, cur, wm, wn, lane, acc);

        const int r0 = wm * 32 + (lane >> 2);
        #pragma unroll
        for (int i = 0; i < 2; i++) {
            #pragma unroll
            for (int j = 0; j < 4; j++) {
                int c = nt * 64 + wn * 32 + j * 8 + 2 * (lane & 3);
                float b0 = __ldg(proj_b + c), b1 = __ldg(proj_b + c + 1);
                #pragma unroll
                for (int half = 0; half < 2; half++) {
                    int row = r0 + i * 16 + half * 8;
                    int win = win0 + (row >> 6), t = row & 63;
                    int wi = win & 1023, wh = wi >> 5, wc = wi & 31, bb = win >> 10;
                    int h = (wh * 8 + (t >> 3) + SHIFT) & 255;
                    int w = (wc * 8 + (t & 7) + SHIFT) & 255;
                    int pix = (h << 8) + w;
                    out[(bb * 192 + c) * 65536 + pix]     = acc[i][j][half * 2 + 0] + b0;
                    out[(bb * 192 + c + 1) * 65536 + pix] = acc[i][j][half * 2 + 1] + b1;
                }
            }
        }
        __syncthreads();
    }
}

// ---------------- launch ------------------------------------------------------
extern "C" void kernel_launch(void* const* d_in, const int* in_sizes, int n_in,
                              void* d_out, int out_size) {
    const float* x      = (const float*)d_in[0];
    const float* qkv_w  = (const float*)d_in[1];
    const float* qkv_b  = (const float*)d_in[2];
    const float* proj_w = (const float*)d_in[3];
    const float* proj_b = (const float*)d_in[4];
    const float* rpb    = (const float*)d_in[5];
    float* out = (float*)d_out;

    cudaFuncSetAttribute(qkv_mma_kernel,  cudaFuncAttributeMaxDynamicSharedMemorySize, SM_BYTES);
    cudaFuncSetAttribute(proj_mma_kernel, cudaFuncAttributeMaxDynamicSharedMemorySize, SM_BYTES);

    prep_bq_kernel<<<(576 * 192 + 255) / 256, 256>>>(qkv_w);
    prep_bp_kernel<<<(192 * 192 + 255) / 256, 256>>>(proj_w);
    qkv_mma_kernel<<<NWIN / 2, 256, SM_BYTES>>>(x, qkv_b);
    attn_kernel<<<NWIN * HEADS, 256>>>(rpb);
    proj_mma_kernel<<<NWIN / 2, 256, SM_BYTES>>>(proj_b, out);
}